// round 4
// baseline (speedup 1.0000x reference)
#include <cuda_runtime.h>
#include <math.h>

#define TT   512
#define DD   512
#define NTOK 1024          // B*T
#define NTH  256           // threads per token-block
#define CPT  2             // d-values per thread (NTH*CPT = DD)
#define NW   (NTH / 32)    // 8 warps

// 3-term Cody-Waite split of 2*pi (q*c1, q*c2 exact for q <= 4096; max q ~ 4083)
#define CW_C1      6.283203125f
#define CW_C2     -1.7821788788e-5f
#define CW_C3      3.968374e-9f
#define INV_2PI    0.15915494309189533576888376337251f

__device__ __forceinline__ float warp_sum(float v) {
    v += __shfl_down_sync(0xffffffffu, v, 16);
    v += __shfl_down_sync(0xffffffffu, v, 8);
    v += __shfl_down_sync(0xffffffffu, v, 4);
    v += __shfl_down_sync(0xffffffffu, v, 2);
    v += __shfl_down_sync(0xffffffffu, v, 1);
    return v;
}

__global__ __launch_bounds__(NTH, 7) void k_fused(
    const int*   __restrict__ token_ids,
    const float* __restrict__ resonances,
    const float* __restrict__ emb_scales,
    const float* __restrict__ emb_shifts,
    const float* __restrict__ emb_norm,
    const float* __restrict__ frac_norm,
    const float* __restrict__ W_enc,     // [512,24]
    const float* __restrict__ b_enc,     // [24]
    const float* __restrict__ W_dec,     // [24,512]
    const float* __restrict__ b_dec,     // [512]
    const float* __restrict__ ecc_strength,
    const float* __restrict__ energy_pres,
    float*       __restrict__ out)
{
    __shared__ float red[NW];
    __shared__ float smat[NTH * 25];     // proj partials, stride 25 (odd: conflict-free writes)
    __shared__ float psum[24 * 8];
    __shared__ float sproj[24];
    __shared__ float slatt[12];
    __shared__ float scorr[24];
    __shared__ float s_ein2;

    const int tok = blockIdx.x;          // b*T + t
    const int t   = tok & (TT - 1);
    const int tid = threadIdx.x;
    const int w   = tid >> 5;
    const int d0  = tid * CPT;

    const float ep    = energy_pres[0];

    // ---- embedding (UNNORMALIZED: normalization deferred past the proj reduction) ----
    const int   id = token_ids[tok];
    const float tv = __fdiv_rn((float)(id % 1000000), 1e6f);
    const float x  = tv + (float)t;

    const float2 res2 = reinterpret_cast<const float2*>(resonances + d0)[0];
    const float2 scl2v= reinterpret_cast<const float2*>(emb_scales + d0)[0];
    const float2 shf2 = reinterpret_cast<const float2*>(emb_shifts + d0)[0];
    const float rr[CPT] = {res2.x, res2.y};
    const float sl[CPT] = {scl2v.x, scl2v.y};
    const float sh[CPT] = {shf2.x, shf2.y};

    float e[CPT];
    float ss = 0.f;
    #pragma unroll
    for (int i = 0; i < CPT; i++) {
        float angle = __fmul_rn(rr[i], x);
        float q  = rintf(angle * INV_2PI);
        float rf = fmaf(q, -CW_C1, angle);
        rf       = fmaf(q, -CW_C2, rf);
        rf       = fmaf(q, -CW_C3, rf);
        float sn = __sinf(rf);
        float cs = __cosf(rf);
        float comp = fmaf(cs, 1.f + sn, sn * sn);
        float v = fmaf(comp, sl[i], sh[i]);
        e[i] = v;
        ss = fmaf(v, v, ss);
    }

    // ---- proj partials from RAW e (scale applied after reduction; linearity) ----
    float p[24];
    #pragma unroll
    for (int k = 0; k < 24; k++) p[k] = 0.f;
    #pragma unroll
    for (int i = 0; i < CPT; i++) {
        const float4* wr = reinterpret_cast<const float4*>(W_enc + (d0 + i) * 24);
        const float ev = e[i];
        #pragma unroll
        for (int j = 0; j < 6; j++) {
            float4 wv = wr[j];
            p[4 * j + 0] = fmaf(ev, wv.x, p[4 * j + 0]);
            p[4 * j + 1] = fmaf(ev, wv.y, p[4 * j + 1]);
            p[4 * j + 2] = fmaf(ev, wv.z, p[4 * j + 2]);
            p[4 * j + 3] = fmaf(ev, wv.w, p[4 * j + 3]);
        }
    }
    #pragma unroll
    for (int k = 0; k < 24; k++) smat[tid * 25 + k] = p[k];
    // emb-norm partials ride under the same barrier
    float wss = warp_sum(ss);
    if ((tid & 31) == 0) red[w] = wss;
    __syncthreads();                                    // S1

    if (tid < 192) {                     // stage 1: 8 partial sums per k
        const int k = tid >> 3, part = tid & 7;
        float s = 0.f;
        #pragma unroll
        for (int j = 0; j < NTH / 8; j++) s += smat[(part + 8 * j) * 25 + k];
        psum[k * 8 + part] = s;
    }
    __syncthreads();                                    // S2

    // ---- stage 2 + norm-apply + Golay enc/round/rescale/dec/threshold: ONE warp ----
    if (tid < 32) {
        float tn2 = red[0] + red[1] + red[2] + red[3] + red[4] + red[5] + red[6] + red[7];
        float tnorm = sqrtf(tn2);
        const float enorm = emb_norm[0];
        float sc_emb = (tnorm > 0.f) ? (enorm / tnorm) : 1.f;
        float e_in   = (tnorm > 0.f) ? enorm : 0.f;     // == tnorm*sc_emb
        if (tid < 24) {
            float s = 0.f;
            #pragma unroll
            for (int q = 0; q < 8; q++) s += psum[tid * 8 + q];
            sproj[tid] = fmaf(sc_emb, s, b_enc[tid]);
        }
        __syncwarp();
        const float ecc = ecc_strength[0];
        // G[i,l] = (l==i) + (12<=l<23)*((i+l-12)&1) + (l==23)*(i&1)
        float S_odd  = sproj[13] + sproj[15] + sproj[17] + sproj[19] + sproj[21];
        float S_even = sproj[12] + sproj[14] + sproj[16] + sproj[18] + sproj[20] + sproj[22];
        float lat = 0.f, lsq = 0.f;
        if (tid < 12) {
            float ge = sproj[tid] + ((tid & 1) ? (S_even + sproj[23]) : S_odd);
            lat = rintf(__fdiv_rn(ge, ecc)) * ecc;      // round-half-even = jnp.round
            lsq = lat * lat;
        }
        float eout2 = warp_sum(lsq);
        eout2 = __shfl_sync(0xffffffffu, eout2, 0);
        float eout = sqrtf(eout2);
        float scl  = e_in / (eout + 1e-8f) * ep;
        if (tid < 12) slatt[tid] = lat * scl;
        if (tid == 0) s_ein2 = scl * eout;              // ||latt|| after scaling
        __syncwarp();
        float L_odd  = slatt[1] + slatt[3] + slatt[5] + slatt[7] + slatt[9] + slatt[11];
        float L_even = slatt[0] + slatt[2] + slatt[4] + slatt[6] + slatt[8] + slatt[10];
        if (tid < 24) {
            float gd;
            if (tid < 12)      gd = slatt[tid];
            else if (tid < 23) gd = ((tid - 12) & 1) ? L_even : L_odd;
            else               gd = L_odd;
            scorr[tid] = (fabsf(gd) > ecc) ? gd : 0.f;
        }
    }
    __syncthreads();                                    // S3

    // ---- res = corrected @ W_dec + b_dec  (coalesced float2 on d) ----
    float2 rv = reinterpret_cast<const float2*>(b_dec)[tid];
    #pragma unroll
    for (int l = 0; l < 24; l++) {
        const float c = scorr[l];
        float2 wv = reinterpret_cast<const float2*>(W_dec + l * DD)[tid];
        rv.x = fmaf(c, wv.x, rv.x);
        rv.y = fmaf(c, wv.y, rv.y);
    }
    float ss2 = fmaf(rv.x, rv.x, rv.y * rv.y);
    float wss2 = warp_sum(ss2);
    if ((tid & 31) == 0) red[w] = wss2;
    __syncthreads();                                    // S4
    float eo2sq = red[0] + red[1] + red[2] + red[3] + red[4] + red[5] + red[6] + red[7];
    float eo2   = sqrtf(eo2sq);
    // global fractal factor folds in analytically: f = frac_norm*32*emb_norm*ep^2
    const float fglob = frac_norm[0] * 32.0f * emb_norm[0] * ep * ep;
    float sfin  = s_ein2 / (eo2 + 1e-8f) * ep * fglob;
    rv.x *= sfin; rv.y *= sfin;
    reinterpret_cast<float2*>(out + tok * DD)[tid] = rv;
}

extern "C" void kernel_launch(void* const* d_in, const int* in_sizes, int n_in,
                              void* d_out, int out_size) {
    (void)in_sizes; (void)n_in; (void)out_size;
    const int*   token_ids    = (const int*)  d_in[0];
    const float* resonances   = (const float*)d_in[1];
    const float* emb_scales   = (const float*)d_in[2];
    const float* emb_shifts   = (const float*)d_in[3];
    const float* emb_norm     = (const float*)d_in[4];
    // d_in[5] scale_weights, d_in[6] fractal_bias: cancel exactly in the math
    const float* frac_norm    = (const float*)d_in[7];
    const float* W_enc        = (const float*)d_in[8];
    const float* b_enc        = (const float*)d_in[9];
    const float* W_dec        = (const float*)d_in[10];
    const float* b_dec        = (const float*)d_in[11];
    const float* ecc_strength = (const float*)d_in[12];
    const float* energy_pres  = (const float*)d_in[13];
    float* out = (float*)d_out;

    k_fused<<<NTOK, NTH>>>(token_ids, resonances, emb_scales, emb_shifts, emb_norm,
                           frac_norm, W_enc, b_enc, W_dec, b_dec,
                           ecc_strength, energy_pres, out);
}

// round 5
// speedup vs baseline: 2.6785x; 2.6785x over previous
#include <cuda_runtime.h>
#include <math.h>

#define TT   512
#define DD   512
#define NTOK 1024          // B*T
#define NTH  256           // threads per token-block
#define CPT  2             // d-values per thread (NTH*CPT = DD)
#define NW   (NTH / 32)    // 8 warps
#define PROJ_TH 192        // 6 col-groups x 32 row-slices
#define ROWS_PER_TH 16     // 512 rows / 32 row-slices
#define SRED_STRIDE 33     // padded: conflict-free column reads

// 3-term Cody-Waite split of 2*pi (q*c1, q*c2 exact for q <= 4096; max q ~ 4083)
#define CW_C1      6.283203125f
#define CW_C2     -1.7821788788e-5f
#define CW_C3      3.968374e-9f
#define INV_2PI    0.15915494309189533576888376337251f

__device__ __forceinline__ float warp_sum(float v) {
    v += __shfl_down_sync(0xffffffffu, v, 16);
    v += __shfl_down_sync(0xffffffffu, v, 8);
    v += __shfl_down_sync(0xffffffffu, v, 4);
    v += __shfl_down_sync(0xffffffffu, v, 2);
    v += __shfl_down_sync(0xffffffffu, v, 1);
    return v;
}

__global__ __launch_bounds__(NTH, 7) void k_fused(
    const int*   __restrict__ token_ids,
    const float* __restrict__ resonances,
    const float* __restrict__ emb_scales,
    const float* __restrict__ emb_shifts,
    const float* __restrict__ emb_norm,
    const float* __restrict__ frac_norm,
    const float* __restrict__ W_enc,     // [512,24]
    const float* __restrict__ b_enc,     // [24]
    const float* __restrict__ W_dec,     // [24,512]
    const float* __restrict__ b_dec,     // [512]
    const float* __restrict__ ecc_strength,
    const float* __restrict__ energy_pres,
    float*       __restrict__ out)
{
    __shared__ float red[NW];
    __shared__ float se[DD];                 // raw embedding
    __shared__ float sred[24 * SRED_STRIDE]; // proj partials [k][r-slice], padded
    __shared__ float sproj[24];
    __shared__ float slatt[12];
    __shared__ float scorr[24];
    __shared__ float s_ein2;

    const int tok = blockIdx.x;          // b*T + t
    const int t   = tok & (TT - 1);
    const int tid = threadIdx.x;
    const int w   = tid >> 5;
    const int d0  = tid * CPT;

    const float ep = energy_pres[0];

    // ---- embedding (raw; normalization deferred past the proj reduction) ----
    const int   id = token_ids[tok];
    const float tv = __fdiv_rn((float)(id % 1000000), 1e6f);
    const float x  = tv + (float)t;

    const float2 res2 = reinterpret_cast<const float2*>(resonances + d0)[0];
    const float2 scl2v= reinterpret_cast<const float2*>(emb_scales + d0)[0];
    const float2 shf2 = reinterpret_cast<const float2*>(emb_shifts + d0)[0];
    const float rr[CPT] = {res2.x, res2.y};
    const float sl[CPT] = {scl2v.x, scl2v.y};
    const float sh[CPT] = {shf2.x, shf2.y};

    float2 ev2;
    float ss = 0.f;
    {
        float ebuf[CPT];
        #pragma unroll
        for (int i = 0; i < CPT; i++) {
            float angle = __fmul_rn(rr[i], x);
            float q  = rintf(angle * INV_2PI);
            float rf = fmaf(q, -CW_C1, angle);
            rf       = fmaf(q, -CW_C2, rf);
            rf       = fmaf(q, -CW_C3, rf);
            float sn = __sinf(rf);
            float cs = __cosf(rf);
            float comp = fmaf(cs, 1.f + sn, sn * sn);
            float v = fmaf(comp, sl[i], sh[i]);
            ebuf[i] = v;
            ss = fmaf(v, v, ss);
        }
        ev2.x = ebuf[0]; ev2.y = ebuf[1];
    }
    reinterpret_cast<float2*>(se)[tid] = ev2;
    float wss = warp_sum(ss);
    if ((tid & 31) == 0) red[w] = wss;
    __syncthreads();                                    // S1: se + norm partials ready

    // ---- proj partials: fully-coalesced W_enc sweep ----
    // W_enc viewed as 3072 float4s. Thread tid (<192): g = tid%6 (k-group),
    // r = tid/6 (row slice). Iter j: float4 index tid + 192*j  -> 192
    // consecutive float4s (perfect coalescing); row = r + 32*j, cols 4g..4g+3.
    if (tid < PROJ_TH) {
        const int g = tid % 6;
        const int r = tid / 6;
        const float4* W4 = reinterpret_cast<const float4*>(W_enc);
        float p0 = 0.f, p1 = 0.f, p2 = 0.f, p3 = 0.f;
        #pragma unroll
        for (int j = 0; j < ROWS_PER_TH; j++) {
            float4 wv = W4[tid + PROJ_TH * j];
            float evr = se[r + 32 * j];              // broadcast, conflict-free
            p0 = fmaf(evr, wv.x, p0);
            p1 = fmaf(evr, wv.y, p1);
            p2 = fmaf(evr, wv.z, p2);
            p3 = fmaf(evr, wv.w, p3);
        }
        const int kb = 4 * g;
        sred[(kb + 0) * SRED_STRIDE + r] = p0;
        sred[(kb + 1) * SRED_STRIDE + r] = p1;
        sred[(kb + 2) * SRED_STRIDE + r] = p2;
        sred[(kb + 3) * SRED_STRIDE + r] = p3;
    }
    __syncthreads();                                    // S2

    // ---- norm-apply + proj reduce + Golay enc/round/rescale/dec/threshold: ONE warp ----
    if (tid < 32) {
        float tn2 = red[0] + red[1] + red[2] + red[3] + red[4] + red[5] + red[6] + red[7];
        float tnorm = sqrtf(tn2);
        const float enorm = emb_norm[0];
        float sc_emb = (tnorm > 0.f) ? (enorm / tnorm) : 1.f;
        float e_in   = (tnorm > 0.f) ? enorm : 0.f;     // == tnorm*sc_emb
        if (tid < 24) {
            float s = 0.f;
            #pragma unroll
            for (int q = 0; q < 32; q++) s += sred[tid * SRED_STRIDE + q];
            sproj[tid] = fmaf(sc_emb, s, b_enc[tid]);
        }
        __syncwarp();
        const float ecc = ecc_strength[0];
        // G[i,l] = (l==i) + (12<=l<23)*((i+l-12)&1) + (l==23)*(i&1)
        float S_odd  = sproj[13] + sproj[15] + sproj[17] + sproj[19] + sproj[21];
        float S_even = sproj[12] + sproj[14] + sproj[16] + sproj[18] + sproj[20] + sproj[22];
        float lat = 0.f, lsq = 0.f;
        if (tid < 12) {
            float ge = sproj[tid] + ((tid & 1) ? (S_even + sproj[23]) : S_odd);
            lat = rintf(__fdiv_rn(ge, ecc)) * ecc;      // round-half-even = jnp.round
            lsq = lat * lat;
        }
        float eout2 = warp_sum(lsq);
        eout2 = __shfl_sync(0xffffffffu, eout2, 0);
        float eout = sqrtf(eout2);
        float scl  = e_in / (eout + 1e-8f) * ep;
        if (tid < 12) slatt[tid] = lat * scl;
        if (tid == 0) s_ein2 = scl * eout;              // ||latt|| after scaling
        __syncwarp();
        float L_odd  = slatt[1] + slatt[3] + slatt[5] + slatt[7] + slatt[9] + slatt[11];
        float L_even = slatt[0] + slatt[2] + slatt[4] + slatt[6] + slatt[8] + slatt[10];
        if (tid < 24) {
            float gd;
            if (tid < 12)      gd = slatt[tid];
            else if (tid < 23) gd = ((tid - 12) & 1) ? L_even : L_odd;
            else               gd = L_odd;
            scorr[tid] = (fabsf(gd) > ecc) ? gd : 0.f;
        }
    }
    __syncthreads();                                    // S3

    // ---- res = corrected @ W_dec + b_dec  (coalesced float2 on d) ----
    float2 rv = reinterpret_cast<const float2*>(b_dec)[tid];
    #pragma unroll
    for (int l = 0; l < 24; l++) {
        const float c = scorr[l];
        float2 wv = reinterpret_cast<const float2*>(W_dec + l * DD)[tid];
        rv.x = fmaf(c, wv.x, rv.x);
        rv.y = fmaf(c, wv.y, rv.y);
    }
    float ss2 = fmaf(rv.x, rv.x, rv.y * rv.y);
    float wss2 = warp_sum(ss2);
    if ((tid & 31) == 0) red[w] = wss2;
    __syncthreads();                                    // S4
    float eo2sq = red[0] + red[1] + red[2] + red[3] + red[4] + red[5] + red[6] + red[7];
    float eo2   = sqrtf(eo2sq);
    // global fractal factor folds in analytically: f = frac_norm*32*emb_norm*ep^2
    const float fglob = frac_norm[0] * 32.0f * emb_norm[0] * ep * ep;
    float sfin  = s_ein2 / (eo2 + 1e-8f) * ep * fglob;
    rv.x *= sfin; rv.y *= sfin;
    reinterpret_cast<float2*>(out + tok * DD)[tid] = rv;
}

extern "C" void kernel_launch(void* const* d_in, const int* in_sizes, int n_in,
                              void* d_out, int out_size) {
    (void)in_sizes; (void)n_in; (void)out_size;
    const int*   token_ids    = (const int*)  d_in[0];
    const float* resonances   = (const float*)d_in[1];
    const float* emb_scales   = (const float*)d_in[2];
    const float* emb_shifts   = (const float*)d_in[3];
    const float* emb_norm     = (const float*)d_in[4];
    // d_in[5] scale_weights, d_in[6] fractal_bias: cancel exactly in the math
    const float* frac_norm    = (const float*)d_in[7];
    const float* W_enc        = (const float*)d_in[8];
    const float* b_enc        = (const float*)d_in[9];
    const float* W_dec        = (const float*)d_in[10];
    const float* b_dec        = (const float*)d_in[11];
    const float* ecc_strength = (const float*)d_in[12];
    const float* energy_pres  = (const float*)d_in[13];
    float* out = (float*)d_out;

    k_fused<<<NTOK, NTH>>>(token_ids, resonances, emb_scales, emb_shifts, emb_norm,
                           frac_norm, W_enc, b_enc, W_dec, b_dec,
                           ecc_strength, energy_pres, out);
}